// round 4
// baseline (speedup 1.0000x reference)
#include <cuda_runtime.h>
#include <cuda_bf16.h>
#include <math.h>

#define N_TOK 4096
#define D 128
#define H 8

// Scratch (device globals — no allocations allowed)
__device__ float g_q[H * N_TOK * D];     // 16 MB
__device__ float g_k[H * N_TOK * D];     // 16 MB
__device__ float g_v[H * N_TOK * D];     // 16 MB
__device__ float g_att[N_TOK * H * D];   // 16 MB, [n][h*128+d]

// ---------------------------------------------------------------------------
// Kernel A: q/k/v projections.  C[n][e] = sum_d X[n][d] * W[h][d][e] + b[h][e]
// grid (N/64, 3*H), block 256.  dyn smem: Ws[128][128] + Xs[64][132]
// ---------------------------------------------------------------------------
#define QKV_SMEM ((128 * 128 + 64 * 132) * 4)

__global__ void qkv_kernel(const float* __restrict__ x,
                           const float* __restrict__ Wq, const float* __restrict__ bq,
                           const float* __restrict__ Wk, const float* __restrict__ bk,
                           const float* __restrict__ Wv, const float* __restrict__ bv) {
    extern __shared__ float sm[];
    float* Ws = sm;               // [128][128]
    float* Xs = sm + 128 * 128;   // [64][132]
    const int PX = 132;

    int p = blockIdx.y / H;       // 0=q, 1=k, 2=v
    int h = blockIdx.y % H;
    const float* W = (p == 0) ? Wq : (p == 1) ? Wk : Wv;
    const float* b = (p == 0) ? bq : (p == 1) ? bk : bv;
    float* outp = (p == 0) ? g_q : (p == 1) ? g_k : g_v;

    int tid = threadIdx.x;
    int row0 = blockIdx.x * 64;

    // Fill Ws (4096 float4)
    {
        const float4* Wg = (const float4*)(W + (size_t)h * D * D);
        float4* Ws4 = (float4*)Ws;
        #pragma unroll
        for (int i = tid; i < 128 * 32; i += 256) Ws4[i] = Wg[i];
    }
    // Fill Xs (2048 float4), pad 132
    for (int i = tid; i < 64 * 32; i += 256) {
        int n = i >> 5, d4 = i & 31;
        float4 v4 = ((const float4*)(x + (size_t)(row0 + n) * D))[d4];
        *((float4*)&Xs[n * PX + 4 * d4]) = v4;
    }
    __syncthreads();

    int tx = tid & 15, ty = tid >> 4;
    int c0 = tx * 8, r0 = ty * 4;
    float acc[4][8];
    #pragma unroll
    for (int i = 0; i < 4; i++)
        #pragma unroll
        for (int j = 0; j < 8; j++) acc[i][j] = 0.f;

    #pragma unroll 8
    for (int k = 0; k < 128; k++) {
        float a0 = Xs[(r0 + 0) * PX + k];
        float a1 = Xs[(r0 + 1) * PX + k];
        float a2 = Xs[(r0 + 2) * PX + k];
        float a3 = Xs[(r0 + 3) * PX + k];
        float4 w0 = *(const float4*)&Ws[k * 128 + c0];
        float4 w1 = *(const float4*)&Ws[k * 128 + c0 + 4];
        acc[0][0] += a0 * w0.x; acc[0][1] += a0 * w0.y; acc[0][2] += a0 * w0.z; acc[0][3] += a0 * w0.w;
        acc[0][4] += a0 * w1.x; acc[0][5] += a0 * w1.y; acc[0][6] += a0 * w1.z; acc[0][7] += a0 * w1.w;
        acc[1][0] += a1 * w0.x; acc[1][1] += a1 * w0.y; acc[1][2] += a1 * w0.z; acc[1][3] += a1 * w0.w;
        acc[1][4] += a1 * w1.x; acc[1][5] += a1 * w1.y; acc[1][6] += a1 * w1.z; acc[1][7] += a1 * w1.w;
        acc[2][0] += a2 * w0.x; acc[2][1] += a2 * w0.y; acc[2][2] += a2 * w0.z; acc[2][3] += a2 * w0.w;
        acc[2][4] += a2 * w1.x; acc[2][5] += a2 * w1.y; acc[2][6] += a2 * w1.z; acc[2][7] += a2 * w1.w;
        acc[3][0] += a3 * w0.x; acc[3][1] += a3 * w0.y; acc[3][2] += a3 * w0.z; acc[3][3] += a3 * w0.w;
        acc[3][4] += a3 * w1.x; acc[3][5] += a3 * w1.y; acc[3][6] += a3 * w1.z; acc[3][7] += a3 * w1.w;
    }

    float4 bb0 = *(const float4*)&b[h * D + c0];
    float4 bb1 = *(const float4*)&b[h * D + c0 + 4];
    #pragma unroll
    for (int i = 0; i < 4; i++) {
        size_t base = ((size_t)h * N_TOK + row0 + r0 + i) * D;
        float4 o0 = make_float4(acc[i][0] + bb0.x, acc[i][1] + bb0.y,
                                acc[i][2] + bb0.z, acc[i][3] + bb0.w);
        float4 o1 = make_float4(acc[i][4] + bb1.x, acc[i][5] + bb1.y,
                                acc[i][6] + bb1.z, acc[i][7] + bb1.w);
        *(float4*)&outp[base + c0] = o0;
        *(float4*)&outp[base + c0 + 4] = o1;
    }
}

// ---------------------------------------------------------------------------
// Kernel B: streaming attention per head.
//   S[n][m] = sum_d v[n][d] q[m][d];  P = softmax_m(S);  out[n][d] = P @ k
// grid (N/64, H), block 256.
// smem: VtT[128][68] + QtT[128][68] + Kt[64][128] + Ssm[64][68] + small
// ---------------------------------------------------------------------------
#define PT 68
#define PS 68
#define ATTN_SMEM ((128 * PT * 2 + 64 * 128 + 64 * PS + 64 * 3 + 4 * 64) * 4)

__global__ void attn_kernel() {
    extern __shared__ float sm[];
    float* VtT = sm;                    // [128][68]  (d-major, transposed)
    float* QtT = VtT + 128 * PT;        // [128][68]
    float* Kt  = QtT + 128 * PT;        // [64][128]
    float* Ssm = Kt + 64 * 128;         // [64][68]
    float* m_s = Ssm + 64 * PS;         // [64]
    float* l_s = m_s + 64;              // [64]
    float* fac = l_s + 64;              // [64]
    float* red = fac + 64;              // [4][64]

    int h = blockIdx.y;
    int bx = blockIdx.x;
    int tid = threadIdx.x;
    int tx = tid & 15, ty = tid >> 4;
    int r0  = ty * 4;   // local rows (n)
    int c0  = tx * 4;   // S columns (GEMM1)
    int c0b = tx * 8;   // output columns (GEMM2)
    int lane = tid & 31, grp = tid >> 5;

    // Load V tile transposed: VtT[d][n] = v[h][bx*64+n][d]
    {
        const float* vg = g_v + ((size_t)h * N_TOK + bx * 64) * D;
        #pragma unroll
        for (int half = 0; half < 2; half++) {
            int n = half * 32 + lane;
            #pragma unroll
            for (int dd = 0; dd < 4; dd++) {
                int d4 = grp + dd * 8;
                float4 v4 = ((const float4*)(vg + (size_t)n * D))[d4];
                VtT[(4 * d4 + 0) * PT + n] = v4.x;
                VtT[(4 * d4 + 1) * PT + n] = v4.y;
                VtT[(4 * d4 + 2) * PT + n] = v4.z;
                VtT[(4 * d4 + 3) * PT + n] = v4.w;
            }
        }
    }
    if (tid < 64) { m_s[tid] = -INFINITY; l_s[tid] = 0.f; }

    float acc[4][8];
    #pragma unroll
    for (int i = 0; i < 4; i++)
        #pragma unroll
        for (int j = 0; j < 8; j++) acc[i][j] = 0.f;

    for (int jt = 0; jt < N_TOK / 64; jt++) {
        __syncthreads();   // prev GEMM2 done reading Kt; VtT load covered too
        // Fill QtT (transposed) and Kt (row-major)
        {
            const float* qg = g_q + ((size_t)h * N_TOK + jt * 64) * D;
            const float* kg = g_k + ((size_t)h * N_TOK + jt * 64) * D;
            #pragma unroll
            for (int half = 0; half < 2; half++) {
                int n = half * 32 + lane;
                #pragma unroll
                for (int dd = 0; dd < 4; dd++) {
                    int d4 = grp + dd * 8;
                    float4 v4 = ((const float4*)(qg + (size_t)n * D))[d4];
                    QtT[(4 * d4 + 0) * PT + n] = v4.x;
                    QtT[(4 * d4 + 1) * PT + n] = v4.y;
                    QtT[(4 * d4 + 2) * PT + n] = v4.z;
                    QtT[(4 * d4 + 3) * PT + n] = v4.w;
                }
            }
            for (int i = tid; i < 64 * 32; i += 256) {
                int n = i >> 5, d4 = i & 31;
                ((float4*)(Kt + n * D))[d4] = ((const float4*)(kg + (size_t)n * D))[d4];
            }
        }
        __syncthreads();

        // ---- GEMM1: S = Vtile @ Qtile^T  (64x64, K=128) ----
        float s[4][4];
        #pragma unroll
        for (int i = 0; i < 4; i++)
            #pragma unroll
            for (int j = 0; j < 4; j++) s[i][j] = 0.f;

        #pragma unroll 8
        for (int k = 0; k < 128; k++) {
            float4 a = *(const float4*)&VtT[k * PT + r0];
            float4 b = *(const float4*)&QtT[k * PT + c0];
            s[0][0] += a.x * b.x; s[0][1] += a.x * b.y; s[0][2] += a.x * b.z; s[0][3] += a.x * b.w;
            s[1][0] += a.y * b.x; s[1][1] += a.y * b.y; s[1][2] += a.y * b.z; s[1][3] += a.y * b.w;
            s[2][0] += a.z * b.x; s[2][1] += a.z * b.y; s[2][2] += a.z * b.z; s[2][3] += a.z * b.w;
            s[3][0] += a.w * b.x; s[3][1] += a.w * b.y; s[3][2] += a.w * b.z; s[3][3] += a.w * b.w;
        }
        #pragma unroll
        for (int i = 0; i < 4; i++) {
            *(float4*)&Ssm[(r0 + i) * PS + c0] =
                make_float4(s[i][0], s[i][1], s[i][2], s[i][3]);
        }
        __syncthreads();

        // ---- online softmax over this 64-wide chunk ----
        int row = tid & 63, part = tid >> 6;
        {
            const float4* srow = (const float4*)&Ssm[row * PS + part * 16];
            float lmax = -INFINITY;
            #pragma unroll
            for (int q4 = 0; q4 < 4; q4++) {
                float4 v4 = srow[q4];
                lmax = fmaxf(lmax, fmaxf(fmaxf(v4.x, v4.y), fmaxf(v4.z, v4.w)));
            }
            red[part * 64 + row] = lmax;
        }
        __syncthreads();
        if (tid < 64) {
            float mo = m_s[tid];
            float mn = fmaxf(fmaxf(red[tid], red[64 + tid]),
                             fmaxf(red[128 + tid], red[192 + tid]));
            mn = fmaxf(mo, mn);
            m_s[tid] = mn;
            fac[tid] = __expf(mo - mn);
        }
        __syncthreads();
        {
            float mn = m_s[row];
            float lsum = 0.f;
            float4* prow = (float4*)&Ssm[row * PS + part * 16];
            #pragma unroll
            for (int q4 = 0; q4 < 4; q4++) {
                float4 v4 = prow[q4];
                v4.x = __expf(v4.x - mn);
                v4.y = __expf(v4.y - mn);
                v4.z = __expf(v4.z - mn);
                v4.w = __expf(v4.w - mn);
                lsum += v4.x + v4.y + v4.z + v4.w;
                prow[q4] = v4;
            }
            red[part * 64 + row] = lsum;
        }
        __syncthreads();
        if (tid < 64) {
            l_s[tid] = l_s[tid] * fac[tid] +
                       red[tid] + red[64 + tid] + red[128 + tid] + red[192 + tid];
        }

        // ---- rescale acc, then GEMM2: acc += P @ Ktile (64x128, K=64) ----
        #pragma unroll
        for (int i = 0; i < 4; i++) {
            float f = fac[r0 + i];
            #pragma unroll
            for (int j = 0; j < 8; j++) acc[i][j] *= f;
        }
        #pragma unroll 4
        for (int k = 0; k < 64; k++) {
            float4 b0 = *(const float4*)&Kt[k * D + c0b];
            float4 b1 = *(const float4*)&Kt[k * D + c0b + 4];
            #pragma unroll
            for (int i = 0; i < 4; i++) {
                float p = Ssm[(r0 + i) * PS + k];
                acc[i][0] += p * b0.x; acc[i][1] += p * b0.y;
                acc[i][2] += p * b0.z; acc[i][3] += p * b0.w;
                acc[i][4] += p * b1.x; acc[i][5] += p * b1.y;
                acc[i][6] += p * b1.z; acc[i][7] += p * b1.w;
            }
        }
    }
    __syncthreads();  // l_s final values visible

    #pragma unroll
    for (int i = 0; i < 4; i++) {
        float inv = 1.f / l_s[r0 + i];
        size_t base = (size_t)(bx * 64 + r0 + i) * (H * D) + h * D + c0b;
        float4 o0 = make_float4(acc[i][0] * inv, acc[i][1] * inv,
                                acc[i][2] * inv, acc[i][3] * inv);
        float4 o1 = make_float4(acc[i][4] * inv, acc[i][5] * inv,
                                acc[i][6] * inv, acc[i][7] * inv);
        *(float4*)&g_att[base] = o0;
        *(float4*)&g_att[base + 4] = o1;
    }
}

// ---------------------------------------------------------------------------
// Kernel C: out = g_att[4096,1024] @ Wo[1024,128] + bo
// grid (N/32), block 256.  static smem < 48 KB
// ---------------------------------------------------------------------------
__global__ void oproj_kernel(const float* __restrict__ Wo,
                             const float* __restrict__ bo,
                             float* __restrict__ out) {
    __shared__ float As[32 * 68];
    __shared__ float Bs[64 * 132];
    int tid = threadIdx.x;
    int bx = blockIdx.x;
    int tx = tid & 31, ty = tid >> 5;
    int c0 = tx * 4, r0 = ty * 4;

    float acc[4][4];
    #pragma unroll
    for (int i = 0; i < 4; i++)
        #pragma unroll
        for (int j = 0; j < 4; j++) acc[i][j] = 0.f;

    for (int kc = 0; kc < 16; kc++) {
        __syncthreads();
        for (int i = tid; i < 512; i += 256) {
            int n = i >> 4, k4 = i & 15;
            *(float4*)&As[n * 68 + 4 * k4] =
                *(const float4*)&g_att[(size_t)(bx * 32 + n) * 1024 + kc * 64 + 4 * k4];
        }
        for (int i = tid; i < 2048; i += 256) {
            int k = i >> 5, c4 = i & 31;
            *(float4*)&Bs[k * 132 + 4 * c4] =
                *(const float4*)&Wo[(size_t)(kc * 64 + k) * 128 + 4 * c4];
        }
        __syncthreads();

        #pragma unroll 8
        for (int kk = 0; kk < 64; kk++) {
            float a0 = As[(r0 + 0) * 68 + kk];
            float a1 = As[(r0 + 1) * 68 + kk];
            float a2 = As[(r0 + 2) * 68 + kk];
            float a3 = As[(r0 + 3) * 68 + kk];
            float4 b = *(const float4*)&Bs[kk * 132 + c0];
            acc[0][0] += a0 * b.x; acc[0][1] += a0 * b.y; acc[0][2] += a0 * b.z; acc[0][3] += a0 * b.w;
            acc[1][0] += a1 * b.x; acc[1][1] += a1 * b.y; acc[1][2] += a1 * b.z; acc[1][3] += a1 * b.w;
            acc[2][0] += a2 * b.x; acc[2][1] += a2 * b.y; acc[2][2] += a2 * b.z; acc[2][3] += a2 * b.w;
            acc[3][0] += a3 * b.x; acc[3][1] += a3 * b.y; acc[3][2] += a3 * b.z; acc[3][3] += a3 * b.w;
        }
    }

    float4 bb = *(const float4*)&bo[c0];
    #pragma unroll
    for (int i = 0; i < 4; i++) {
        float4 o = make_float4(acc[i][0] + bb.x, acc[i][1] + bb.y,
                               acc[i][2] + bb.z, acc[i][3] + bb.w);
        *(float4*)&out[(size_t)(bx * 32 + r0 + i) * 128 + c0] = o;
    }
}

// ---------------------------------------------------------------------------
extern "C" void kernel_launch(void* const* d_in, const int* in_sizes, int n_in,
                              void* d_out, int out_size) {
    const float* x  = (const float*)d_in[0];
    const float* Wq = (const float*)d_in[1];
    const float* bq = (const float*)d_in[2];
    const float* Wk = (const float*)d_in[3];
    const float* bk = (const float*)d_in[4];
    const float* Wv = (const float*)d_in[5];
    const float* bv = (const float*)d_in[6];
    const float* Wo = (const float*)d_in[7];
    const float* bo = (const float*)d_in[8];
    float* out = (float*)d_out;

    cudaFuncSetAttribute(qkv_kernel, cudaFuncAttributeMaxDynamicSharedMemorySize, QKV_SMEM);
    cudaFuncSetAttribute(attn_kernel, cudaFuncAttributeMaxDynamicSharedMemorySize, ATTN_SMEM);

    qkv_kernel<<<dim3(N_TOK / 64, 3 * H), 256, QKV_SMEM>>>(x, Wq, bq, Wk, bk, Wv, bv);
    attn_kernel<<<dim3(N_TOK / 64, H), 256, ATTN_SMEM>>>();
    oproj_kernel<<<N_TOK / 32, 256>>>(Wo, bo, out);
}

// round 5
// speedup vs baseline: 1.0011x; 1.0011x over previous
#include <cuda_runtime.h>
#include <cuda_bf16.h>
#include <math.h>

#define N_TOK 4096
#define D 128
#define H 8

// Scratch (device globals — no allocations allowed)
__device__ float g_q[H * N_TOK * D];     // 16 MB
__device__ float g_k[H * N_TOK * D];     // 16 MB
__device__ float g_v[H * N_TOK * D];     // 16 MB
__device__ float g_att[N_TOK * H * D];   // 16 MB, [n][h*128+d]

// ---------------------------------------------------------------------------
// Kernel A: q/k/v projections.  C[n][e] = sum_d X[n][d] * W[h][d][e] + b[h][e]
// grid (N/64, 3*H), block 256.  dyn smem: Ws[128][128] + Xs[64][132]
// ---------------------------------------------------------------------------
#define QKV_SMEM ((128 * 128 + 64 * 132) * 4)

__global__ void qkv_kernel(const float* __restrict__ x,
                           const float* __restrict__ Wq, const float* __restrict__ bq,
                           const float* __restrict__ Wk, const float* __restrict__ bk,
                           const float* __restrict__ Wv, const float* __restrict__ bv) {
    extern __shared__ float sm[];
    float* Ws = sm;               // [128][128]
    float* Xs = sm + 128 * 128;   // [64][132]
    const int PX = 132;

    int p = blockIdx.y / H;       // 0=q, 1=k, 2=v
    int h = blockIdx.y % H;
    const float* W = (p == 0) ? Wq : (p == 1) ? Wk : Wv;
    const float* b = (p == 0) ? bq : (p == 1) ? bk : bv;
    float* outp = (p == 0) ? g_q : (p == 1) ? g_k : g_v;

    int tid = threadIdx.x;
    int row0 = blockIdx.x * 64;

    // Fill Ws (4096 float4)
    {
        const float4* Wg = (const float4*)(W + (size_t)h * D * D);
        float4* Ws4 = (float4*)Ws;
        #pragma unroll
        for (int i = tid; i < 128 * 32; i += 256) Ws4[i] = Wg[i];
    }
    // Fill Xs (2048 float4), pad 132
    for (int i = tid; i < 64 * 32; i += 256) {
        int n = i >> 5, d4 = i & 31;
        float4 v4 = ((const float4*)(x + (size_t)(row0 + n) * D))[d4];
        *((float4*)&Xs[n * PX + 4 * d4]) = v4;
    }
    __syncthreads();

    int tx = tid & 15, ty = tid >> 4;
    int c0 = tx * 8, r0 = ty * 4;
    float acc[4][8];
    #pragma unroll
    for (int i = 0; i < 4; i++)
        #pragma unroll
        for (int j = 0; j < 8; j++) acc[i][j] = 0.f;

    #pragma unroll 8
    for (int k = 0; k < 128; k++) {
        float a0 = Xs[(r0 + 0) * PX + k];
        float a1 = Xs[(r0 + 1) * PX + k];
        float a2 = Xs[(r0 + 2) * PX + k];
        float a3 = Xs[(r0 + 3) * PX + k];
        float4 w0 = *(const float4*)&Ws[k * 128 + c0];
        float4 w1 = *(const float4*)&Ws[k * 128 + c0 + 4];
        acc[0][0] += a0 * w0.x; acc[0][1] += a0 * w0.y; acc[0][2] += a0 * w0.z; acc[0][3] += a0 * w0.w;
        acc[0][4] += a0 * w1.x; acc[0][5] += a0 * w1.y; acc[0][6] += a0 * w1.z; acc[0][7] += a0 * w1.w;
        acc[1][0] += a1 * w0.x; acc[1][1] += a1 * w0.y; acc[1][2] += a1 * w0.z; acc[1][3] += a1 * w0.w;
        acc[1][4] += a1 * w1.x; acc[1][5] += a1 * w1.y; acc[1][6] += a1 * w1.z; acc[1][7] += a1 * w1.w;
        acc[2][0] += a2 * w0.x; acc[2][1] += a2 * w0.y; acc[2][2] += a2 * w0.z; acc[2][3] += a2 * w0.w;
        acc[2][4] += a2 * w1.x; acc[2][5] += a2 * w1.y; acc[2][6] += a2 * w1.z; acc[2][7] += a2 * w1.w;
        acc[3][0] += a3 * w0.x; acc[3][1] += a3 * w0.y; acc[3][2] += a3 * w0.z; acc[3][3] += a3 * w0.w;
        acc[3][4] += a3 * w1.x; acc[3][5] += a3 * w1.y; acc[3][6] += a3 * w1.z; acc[3][7] += a3 * w1.w;
    }

    float4 bb0 = *(const float4*)&b[h * D + c0];
    float4 bb1 = *(const float4*)&b[h * D + c0 + 4];
    #pragma unroll
    for (int i = 0; i < 4; i++) {
        size_t base = ((size_t)h * N_TOK + row0 + r0 + i) * D;
        float4 o0 = make_float4(acc[i][0] + bb0.x, acc[i][1] + bb0.y,
                                acc[i][2] + bb0.z, acc[i][3] + bb0.w);
        float4 o1 = make_float4(acc[i][4] + bb1.x, acc[i][5] + bb1.y,
                                acc[i][6] + bb1.z, acc[i][7] + bb1.w);
        *(float4*)&outp[base + c0] = o0;
        *(float4*)&outp[base + c0 + 4] = o1;
    }
}

// ---------------------------------------------------------------------------
// Kernel B: streaming attention per head.
//   S[n][m] = sum_d v[n][d] q[m][d];  P = softmax_m(S);  out[n][d] = P @ k
// grid (N/64, H), block 256.
// smem: VtT[128][68] + QtT[128][68] + Kt[64][128] + Ssm[64][68] + small
// ---------------------------------------------------------------------------
#define PT 68
#define PS 68
#define ATTN_SMEM ((128 * PT * 2 + 64 * 128 + 64 * PS + 64 * 3 + 4 * 64) * 4)

__global__ void attn_kernel() {
    extern __shared__ float sm[];
    float* VtT = sm;                    // [128][68]  (d-major, transposed)
    float* QtT = VtT + 128 * PT;        // [128][68]
    float* Kt  = QtT + 128 * PT;        // [64][128]
    float* Ssm = Kt + 64 * 128;         // [64][68]
    float* m_s = Ssm + 64 * PS;         // [64]
    float* l_s = m_s + 64;              // [64]
    float* fac = l_s + 64;              // [64]
    float* red = fac + 64;              // [4][64]

    int h = blockIdx.y;
    int bx = blockIdx.x;
    int tid = threadIdx.x;
    int tx = tid & 15, ty = tid >> 4;
    int r0  = ty * 4;   // local rows (n)
    int c0  = tx * 4;   // S columns (GEMM1)
    int c0b = tx * 8;   // output columns (GEMM2)
    int lane = tid & 31, grp = tid >> 5;

    // Load V tile transposed: VtT[d][n] = v[h][bx*64+n][d]
    {
        const float* vg = g_v + ((size_t)h * N_TOK + bx * 64) * D;
        #pragma unroll
        for (int half = 0; half < 2; half++) {
            int n = half * 32 + lane;
            #pragma unroll
            for (int dd = 0; dd < 4; dd++) {
                int d4 = grp + dd * 8;
                float4 v4 = ((const float4*)(vg + (size_t)n * D))[d4];
                VtT[(4 * d4 + 0) * PT + n] = v4.x;
                VtT[(4 * d4 + 1) * PT + n] = v4.y;
                VtT[(4 * d4 + 2) * PT + n] = v4.z;
                VtT[(4 * d4 + 3) * PT + n] = v4.w;
            }
        }
    }
    if (tid < 64) { m_s[tid] = -INFINITY; l_s[tid] = 0.f; }

    float acc[4][8];
    #pragma unroll
    for (int i = 0; i < 4; i++)
        #pragma unroll
        for (int j = 0; j < 8; j++) acc[i][j] = 0.f;

    for (int jt = 0; jt < N_TOK / 64; jt++) {
        __syncthreads();   // prev GEMM2 done reading Kt; VtT load covered too
        // Fill QtT (transposed) and Kt (row-major)
        {
            const float* qg = g_q + ((size_t)h * N_TOK + jt * 64) * D;
            const float* kg = g_k + ((size_t)h * N_TOK + jt * 64) * D;
            #pragma unroll
            for (int half = 0; half < 2; half++) {
                int n = half * 32 + lane;
                #pragma unroll
                for (int dd = 0; dd < 4; dd++) {
                    int d4 = grp + dd * 8;
                    float4 v4 = ((const float4*)(qg + (size_t)n * D))[d4];
                    QtT[(4 * d4 + 0) * PT + n] = v4.x;
                    QtT[(4 * d4 + 1) * PT + n] = v4.y;
                    QtT[(4 * d4 + 2) * PT + n] = v4.z;
                    QtT[(4 * d4 + 3) * PT + n] = v4.w;
                }
            }
            for (int i = tid; i < 64 * 32; i += 256) {
                int n = i >> 5, d4 = i & 31;
                ((float4*)(Kt + n * D))[d4] = ((const float4*)(kg + (size_t)n * D))[d4];
            }
        }
        __syncthreads();

        // ---- GEMM1: S = Vtile @ Qtile^T  (64x64, K=128) ----
        float s[4][4];
        #pragma unroll
        for (int i = 0; i < 4; i++)
            #pragma unroll
            for (int j = 0; j < 4; j++) s[i][j] = 0.f;

        #pragma unroll 8
        for (int k = 0; k < 128; k++) {
            float4 a = *(const float4*)&VtT[k * PT + r0];
            float4 b = *(const float4*)&QtT[k * PT + c0];
            s[0][0] += a.x * b.x; s[0][1] += a.x * b.y; s[0][2] += a.x * b.z; s[0][3] += a.x * b.w;
            s[1][0] += a.y * b.x; s[1][1] += a.y * b.y; s[1][2] += a.y * b.z; s[1][3] += a.y * b.w;
            s[2][0] += a.z * b.x; s[2][1] += a.z * b.y; s[2][2] += a.z * b.z; s[2][3] += a.z * b.w;
            s[3][0] += a.w * b.x; s[3][1] += a.w * b.y; s[3][2] += a.w * b.z; s[3][3] += a.w * b.w;
        }
        #pragma unroll
        for (int i = 0; i < 4; i++) {
            *(float4*)&Ssm[(r0 + i) * PS + c0] =
                make_float4(s[i][0], s[i][1], s[i][2], s[i][3]);
        }
        __syncthreads();

        // ---- online softmax over this 64-wide chunk ----
        int row = tid & 63, part = tid >> 6;
        {
            const float4* srow = (const float4*)&Ssm[row * PS + part * 16];
            float lmax = -INFINITY;
            #pragma unroll
            for (int q4 = 0; q4 < 4; q4++) {
                float4 v4 = srow[q4];
                lmax = fmaxf(lmax, fmaxf(fmaxf(v4.x, v4.y), fmaxf(v4.z, v4.w)));
            }
            red[part * 64 + row] = lmax;
        }
        __syncthreads();
        if (tid < 64) {
            float mo = m_s[tid];
            float mn = fmaxf(fmaxf(red[tid], red[64 + tid]),
                             fmaxf(red[128 + tid], red[192 + tid]));
            mn = fmaxf(mo, mn);
            m_s[tid] = mn;
            fac[tid] = __expf(mo - mn);
        }
        __syncthreads();
        {
            float mn = m_s[row];
            float lsum = 0.f;
            float4* prow = (float4*)&Ssm[row * PS + part * 16];
            #pragma unroll
            for (int q4 = 0; q4 < 4; q4++) {
                float4 v4 = prow[q4];
                v4.x = __expf(v4.x - mn);
                v4.y = __expf(v4.y - mn);
                v4.z = __expf(v4.z - mn);
                v4.w = __expf(v4.w - mn);
                lsum += v4.x + v4.y + v4.z + v4.w;
                prow[q4] = v4;
            }
            red[part * 64 + row] = lsum;
        }
        __syncthreads();
        if (tid < 64) {
            l_s[tid] = l_s[tid] * fac[tid] +
                       red[tid] + red[64 + tid] + red[128 + tid] + red[192 + tid];
        }

        // ---- rescale acc, then GEMM2: acc += P @ Ktile (64x128, K=64) ----
        #pragma unroll
        for (int i = 0; i < 4; i++) {
            float f = fac[r0 + i];
            #pragma unroll
            for (int j = 0; j < 8; j++) acc[i][j] *= f;
        }
        #pragma unroll 4
        for (int k = 0; k < 64; k++) {
            float4 b0 = *(const float4*)&Kt[k * D + c0b];
            float4 b1 = *(const float4*)&Kt[k * D + c0b + 4];
            #pragma unroll
            for (int i = 0; i < 4; i++) {
                float p = Ssm[(r0 + i) * PS + k];
                acc[i][0] += p * b0.x; acc[i][1] += p * b0.y;
                acc[i][2] += p * b0.z; acc[i][3] += p * b0.w;
                acc[i][4] += p * b1.x; acc[i][5] += p * b1.y;
                acc[i][6] += p * b1.z; acc[i][7] += p * b1.w;
            }
        }
    }
    __syncthreads();  // l_s final values visible

    #pragma unroll
    for (int i = 0; i < 4; i++) {
        float inv = 1.f / l_s[r0 + i];
        size_t base = (size_t)(bx * 64 + r0 + i) * (H * D) + h * D + c0b;
        float4 o0 = make_float4(acc[i][0] * inv, acc[i][1] * inv,
                                acc[i][2] * inv, acc[i][3] * inv);
        float4 o1 = make_float4(acc[i][4] * inv, acc[i][5] * inv,
                                acc[i][6] * inv, acc[i][7] * inv);
        *(float4*)&g_att[base] = o0;
        *(float4*)&g_att[base + 4] = o1;
    }
}

// ---------------------------------------------------------------------------
// Kernel C: out = g_att[4096,1024] @ Wo[1024,128] + bo
// grid (N/32), block 256.  static smem < 48 KB
// ---------------------------------------------------------------------------
__global__ void oproj_kernel(const float* __restrict__ Wo,
                             const float* __restrict__ bo,
                             float* __restrict__ out) {
    __shared__ float As[32 * 68];
    __shared__ float Bs[64 * 132];
    int tid = threadIdx.x;
    int bx = blockIdx.x;
    int tx = tid & 31, ty = tid >> 5;
    int c0 = tx * 4, r0 = ty * 4;

    float acc[4][4];
    #pragma unroll
    for (int i = 0; i < 4; i++)
        #pragma unroll
        for (int j = 0; j < 4; j++) acc[i][j] = 0.f;

    for (int kc = 0; kc < 16; kc++) {
        __syncthreads();
        for (int i = tid; i < 512; i += 256) {
            int n = i >> 4, k4 = i & 15;
            *(float4*)&As[n * 68 + 4 * k4] =
                *(const float4*)&g_att[(size_t)(bx * 32 + n) * 1024 + kc * 64 + 4 * k4];
        }
        for (int i = tid; i < 2048; i += 256) {
            int k = i >> 5, c4 = i & 31;
            *(float4*)&Bs[k * 132 + 4 * c4] =
                *(const float4*)&Wo[(size_t)(kc * 64 + k) * 128 + 4 * c4];
        }
        __syncthreads();

        #pragma unroll 8
        for (int kk = 0; kk < 64; kk++) {
            float a0 = As[(r0 + 0) * 68 + kk];
            float a1 = As[(r0 + 1) * 68 + kk];
            float a2 = As[(r0 + 2) * 68 + kk];
            float a3 = As[(r0 + 3) * 68 + kk];
            float4 b = *(const float4*)&Bs[kk * 132 + c0];
            acc[0][0] += a0 * b.x; acc[0][1] += a0 * b.y; acc[0][2] += a0 * b.z; acc[0][3] += a0 * b.w;
            acc[1][0] += a1 * b.x; acc[1][1] += a1 * b.y; acc[1][2] += a1 * b.z; acc[1][3] += a1 * b.w;
            acc[2][0] += a2 * b.x; acc[2][1] += a2 * b.y; acc[2][2] += a2 * b.z; acc[2][3] += a2 * b.w;
            acc[3][0] += a3 * b.x; acc[3][1] += a3 * b.y; acc[3][2] += a3 * b.z; acc[3][3] += a3 * b.w;
        }
    }

    float4 bb = *(const float4*)&bo[c0];
    #pragma unroll
    for (int i = 0; i < 4; i++) {
        float4 o = make_float4(acc[i][0] + bb.x, acc[i][1] + bb.y,
                               acc[i][2] + bb.z, acc[i][3] + bb.w);
        *(float4*)&out[(size_t)(bx * 32 + r0 + i) * 128 + c0] = o;
    }
}

// ---------------------------------------------------------------------------
extern "C" void kernel_launch(void* const* d_in, const int* in_sizes, int n_in,
                              void* d_out, int out_size) {
    const float* x  = (const float*)d_in[0];
    const float* Wq = (const float*)d_in[1];
    const float* bq = (const float*)d_in[2];
    const float* Wk = (const float*)d_in[3];
    const float* bk = (const float*)d_in[4];
    const float* Wv = (const float*)d_in[5];
    const float* bv = (const float*)d_in[6];
    const float* Wo = (const float*)d_in[7];
    const float* bo = (const float*)d_in[8];
    float* out = (float*)d_out;

    cudaFuncSetAttribute(qkv_kernel, cudaFuncAttributeMaxDynamicSharedMemorySize, QKV_SMEM);
    cudaFuncSetAttribute(attn_kernel, cudaFuncAttributeMaxDynamicSharedMemorySize, ATTN_SMEM);

    qkv_kernel<<<dim3(N_TOK / 64, 3 * H), 256, QKV_SMEM>>>(x, Wq, bq, Wk, bk, Wv, bv);
    attn_kernel<<<dim3(N_TOK / 64, H), 256, ATTN_SMEM>>>();
    oproj_kernel<<<N_TOK / 32, 256>>>(Wo, bo, out);
}

// round 7
// speedup vs baseline: 3.2394x; 3.2357x over previous
#include <cuda_runtime.h>
#include <cuda_bf16.h>
#include <mma.h>
#include <math.h>
#include <stdint.h>

#define N_TOK 4096
#define D 128
#define H 8

using namespace nvcuda;

typedef wmma::fragment<wmma::matrix_a, 16, 16, 16, __nv_bfloat16, wmma::row_major> FragA;
typedef wmma::fragment<wmma::matrix_b, 16, 16, 16, __nv_bfloat16, wmma::col_major> FragB;
typedef wmma::fragment<wmma::accumulator, 16, 16, 16, float> FragC;

// ===========================================================================
// Device-global scratch (no allocations allowed)
// ===========================================================================
__device__ __nv_bfloat16 g_x_hi[N_TOK * D],      g_x_lo[N_TOK * D];
__device__ __nv_bfloat16 g_Wt_hi[3 * H * D * D], g_Wt_lo[3 * H * D * D];   // [p][h][e][d]
__device__ __nv_bfloat16 g_WoT_hi[D * H * D],    g_WoT_lo[D * H * D];      // [f][c]
__device__ __nv_bfloat16 g_q_hi[H * N_TOK * D],  g_q_lo[H * N_TOK * D];    // [h][n][d]
__device__ __nv_bfloat16 g_v_hi[H * N_TOK * D],  g_v_lo[H * N_TOK * D];    // [h][n][d]
__device__ __nv_bfloat16 g_kT_hi[H * D * N_TOK], g_kT_lo[H * D * N_TOK];   // [h][e][m]
__device__ __nv_bfloat16 g_att_hi[N_TOK * H * D], g_att_lo[N_TOK * H * D]; // [n][h*D+d]

// ===========================================================================
// SMEM layout (bytes).  bf16 tiles: 128 rows x stride 136 (=34816 B).
// S region (fp32, 128 x stride 132 = 67584 B) ALIASES the B region.
// ===========================================================================
#define LDB 136          // bf16 tile stride (elems): 136*2B=272B -> bank coeff 4 (conflict-free)
#define LDS_ 132         // fp32 S stride (elems): bank = 4*row + col (conflict-free float4)
#define OFF_MS   0       // float[128] running max
#define OFF_LS   512     // float[128] running sum
#define OFF_FAC  1024    // float[128] rescale factor
#define OFF_RED  1536    // float[256] reduction scratch
#define OFF_BIAS 2560    // float[128]
#define OFF_AHI  4096
#define OFF_ALO  (OFF_AHI + 34816)
#define OFF_BHI  (OFF_ALO + 34816)     // 73728
#define OFF_BLO  (OFF_BHI + 34816)     // 108544
#define OFF_S    OFF_BHI               // fp32 S aliases B (67584 <= 69632)
#define OFF_PHI  (OFF_BLO + 34816)     // 143360
#define OFF_PLO  (OFF_PHI + 34816)     // 178176
#define SM_BYTES (OFF_PLO + 34816)     // 212992

// ===========================================================================
// Helpers
// ===========================================================================
// 3-term split GEMM over K=128: acc += Ah*Bh^T + Ah*Bl^T + Al*Bh^T
// Warp computes 32x64 tile at (r0, c0) of a 128x128 output.
__device__ __forceinline__ void gemm3_tile(FragC acc[2][4],
                                           const __nv_bfloat16* Ahi,
                                           const __nv_bfloat16* Alo,
                                           const __nv_bfloat16* Bhi,
                                           const __nv_bfloat16* Blo,
                                           int r0, int c0) {
    #pragma unroll
    for (int k = 0; k < 8; k++) {
        FragA ah[2], al[2];
        FragB bh[4], bl[4];
        #pragma unroll
        for (int i = 0; i < 2; i++) {
            wmma::load_matrix_sync(ah[i], Ahi + (r0 + 16 * i) * LDB + 16 * k, LDB);
            wmma::load_matrix_sync(al[i], Alo + (r0 + 16 * i) * LDB + 16 * k, LDB);
        }
        #pragma unroll
        for (int j = 0; j < 4; j++) {
            wmma::load_matrix_sync(bh[j], Bhi + (c0 + 16 * j) * LDB + 16 * k, LDB);
            wmma::load_matrix_sync(bl[j], Blo + (c0 + 16 * j) * LDB + 16 * k, LDB);
        }
        #pragma unroll
        for (int i = 0; i < 2; i++)
            #pragma unroll
            for (int j = 0; j < 4; j++) {
                wmma::mma_sync(acc[i][j], ah[i], bh[j], acc[i][j]);
                wmma::mma_sync(acc[i][j], ah[i], bl[j], acc[i][j]);
                wmma::mma_sync(acc[i][j], al[i], bh[j], acc[i][j]);
            }
    }
}

// Load 128x128 bf16 tile (row-major, given row stride) into SMEM [128][LDB]
__device__ __forceinline__ void ld_tile(const __nv_bfloat16* __restrict__ src,
                                        int stride, __nv_bfloat16* __restrict__ dst) {
    int tid = threadIdx.x;
    #pragma unroll
    for (int it = 0; it < 8; it++) {
        int idx = tid + it * 256;
        int row = idx >> 4, c16 = idx & 15;
        *(uint4*)(dst + row * LDB + c16 * 8) =
            *(const uint4*)(src + (size_t)row * stride + c16 * 8);
    }
}

__device__ __forceinline__ uint32_t pack_hi(float a, float b, float& la, float& lb) {
    __nv_bfloat162 t = __floats2bfloat162_rn(a, b);
    la = a - __bfloat162float(t.x);
    lb = b - __bfloat162float(t.y);
    return *reinterpret_cast<uint32_t*>(&t);
}
__device__ __forceinline__ uint32_t pack2(float a, float b) {
    __nv_bfloat162 t = __floats2bfloat162_rn(a, b);
    return *reinterpret_cast<uint32_t*>(&t);
}

// ===========================================================================
// Kernel 0: split + transpose prep for x, Wq/Wk/Wv, Wo
// ===========================================================================
__global__ void prep_kernel(const float* __restrict__ x,
                            const float* __restrict__ Wq, const float* __restrict__ Wk,
                            const float* __restrict__ Wv, const float* __restrict__ Wo) {
    int stride = gridDim.x * blockDim.x;
    int t0 = blockIdx.x * blockDim.x + threadIdx.x;
    for (int i = t0; i < N_TOK * D; i += stride) {
        float v = x[i];
        __nv_bfloat16 hi = __float2bfloat16_rn(v);
        g_x_hi[i] = hi;
        g_x_lo[i] = __float2bfloat16_rn(v - __bfloat162float(hi));
    }
    for (int i = t0; i < 3 * H * D * D; i += stride) {
        int p = i >> 17;
        int r = i & 131071;
        int h = r >> 14;
        int d = (r >> 7) & 127;
        int e = r & 127;
        const float* W = (p == 0) ? Wq : (p == 1) ? Wk : Wv;
        float v = W[r];
        int dst = ((p * H + h) * D + e) * D + d;
        __nv_bfloat16 hi = __float2bfloat16_rn(v);
        g_Wt_hi[dst] = hi;
        g_Wt_lo[dst] = __float2bfloat16_rn(v - __bfloat162float(hi));
    }
    for (int i = t0; i < (H * D) * D; i += stride) {
        int c = i >> 7, f = i & 127;
        float v = Wo[i];
        int dst = f * (H * D) + c;
        __nv_bfloat16 hi = __float2bfloat16_rn(v);
        g_WoT_hi[dst] = hi;
        g_WoT_lo[dst] = __float2bfloat16_rn(v - __bfloat162float(hi));
    }
}

// ===========================================================================
// Kernel A: qkv projections.  C[n][e] = sum_d x[n][d] Wt[p][h][e][d] + b
// grid (32, 24), block 256.  k written transposed to kT[h][e][m].
// ===========================================================================
__global__ void __launch_bounds__(256, 1)
qkv_tc_kernel(const float* __restrict__ bq, const float* __restrict__ bk,
              const float* __restrict__ bv) {
    extern __shared__ char sm[];
    __nv_bfloat16* Ahi = (__nv_bfloat16*)(sm + OFF_AHI);
    __nv_bfloat16* Alo = (__nv_bfloat16*)(sm + OFF_ALO);
    __nv_bfloat16* Bhi = (__nv_bfloat16*)(sm + OFF_BHI);
    __nv_bfloat16* Blo = (__nv_bfloat16*)(sm + OFF_BLO);
    float* Ssm = (float*)(sm + OFF_PHI);      // C staging (separate from B here)
    float* bias = (float*)(sm + OFF_BIAS);

    int tid = threadIdx.x, wid = tid >> 5;
    int p = blockIdx.y >> 3, h = blockIdx.y & 7;
    int n0 = blockIdx.x * 128;
    int r0 = (wid & 3) * 32, c0 = (wid >> 2) * 64;

    const float* b = (p == 0) ? bq : (p == 1) ? bk : bv;
    if (tid < 128) bias[tid] = b[h * D + tid];

    ld_tile(g_x_hi + (size_t)n0 * D, D, Ahi);
    ld_tile(g_x_lo + (size_t)n0 * D, D, Alo);
    size_t wt = ((size_t)(p * H + h)) * D * D;
    ld_tile(g_Wt_hi + wt, D, Bhi);
    ld_tile(g_Wt_lo + wt, D, Blo);
    __syncthreads();

    FragC acc[2][4];
    #pragma unroll
    for (int i = 0; i < 2; i++)
        #pragma unroll
        for (int j = 0; j < 4; j++) wmma::fill_fragment(acc[i][j], 0.f);

    gemm3_tile(acc, Ahi, Alo, Bhi, Blo, r0, c0);

    #pragma unroll
    for (int i = 0; i < 2; i++)
        #pragma unroll
        for (int j = 0; j < 4; j++)
            wmma::store_matrix_sync(&Ssm[(r0 + 16 * i) * LDS_ + c0 + 16 * j],
                                    acc[i][j], LDS_, wmma::mem_row_major);
    __syncthreads();

    int row = tid & 127, half = tid >> 7;
    if (p == 1) {
        // k -> transposed kT[h][e][m]; coalesced across threads per column
        #pragma unroll
        for (int c = 0; c < 64; c++) {
            int col = half * 64 + c;
            float v = Ssm[row * LDS_ + col] + bias[col];
            __nv_bfloat16 hi = __float2bfloat16_rn(v);
            size_t off = ((size_t)(h * D + col)) * N_TOK + n0 + row;
            g_kT_hi[off] = hi;
            g_kT_lo[off] = __float2bfloat16_rn(v - __bfloat162float(hi));
        }
    } else {
        __nv_bfloat16* oh = ((p == 0) ? g_q_hi : g_v_hi) +
                            ((size_t)h * N_TOK + n0 + row) * D + half * 64;
        __nv_bfloat16* ol = ((p == 0) ? g_q_lo : g_v_lo) +
                            ((size_t)h * N_TOK + n0 + row) * D + half * 64;
        #pragma unroll
        for (int g = 0; g < 8; g++) {
            uint32_t hw[4], lw[4];
            #pragma unroll
            for (int q = 0; q < 4; q++) {
                int col = half * 64 + g * 8 + 2 * q;
                float a = Ssm[row * LDS_ + col]     + bias[col];
                float d2 = Ssm[row * LDS_ + col + 1] + bias[col + 1];
                float la, lb;
                hw[q] = pack_hi(a, d2, la, lb);
                lw[q] = pack2(la, lb);
            }
            ((uint4*)oh)[g] = make_uint4(hw[0], hw[1], hw[2], hw[3]);
            ((uint4*)ol)[g] = make_uint4(lw[0], lw[1], lw[2], lw[3]);
        }
    }
}

// ===========================================================================
// Kernel B: flash attention on WMMA tensor cores.
//   S = Vtile @ Qchunk^T;  P = online-softmax(S);  O += P @ Kchunk
// grid (32, H), block 256.  O lives in accumulator fragments; rescaled via
// SMEM roundtrip only when a row max changes.
// ===========================================================================
__global__ void __launch_bounds__(256, 1) attn_tc_kernel() {
    extern __shared__ char sm[];
    __nv_bfloat16* Ahi = (__nv_bfloat16*)(sm + OFF_AHI);
    __nv_bfloat16* Alo = (__nv_bfloat16*)(sm + OFF_ALO);
    __nv_bfloat16* Bhi = (__nv_bfloat16*)(sm + OFF_BHI);
    __nv_bfloat16* Blo = (__nv_bfloat16*)(sm + OFF_BLO);
    __nv_bfloat16* Phi = (__nv_bfloat16*)(sm + OFF_PHI);
    __nv_bfloat16* Plo = (__nv_bfloat16*)(sm + OFF_PLO);
    float* Ssm = (float*)(sm + OFF_S);        // aliases B region
    float* m_s = (float*)(sm + OFF_MS);
    float* l_s = (float*)(sm + OFF_LS);
    float* fac = (float*)(sm + OFF_FAC);
    float* red = (float*)(sm + OFF_RED);

    int tid = threadIdx.x, wid = tid >> 5;
    int h = blockIdx.y, n0 = blockIdx.x * 128;
    int r0 = (wid & 3) * 32, c0 = (wid >> 2) * 64;
    int row = tid & 127, half = tid >> 7;

    if (tid < 128) { m_s[tid] = -INFINITY; l_s[tid] = 0.f; }

    ld_tile(g_v_hi + ((size_t)h * N_TOK + n0) * D, D, Ahi);
    ld_tile(g_v_lo + ((size_t)h * N_TOK + n0) * D, D, Alo);

    FragC o[2][4];
    #pragma unroll
    for (int i = 0; i < 2; i++)
        #pragma unroll
        for (int j = 0; j < 4; j++) wmma::fill_fragment(o[i][j], 0.f);

    for (int jt = 0; jt < N_TOK / 128; jt++) {
        // ---- Q chunk -> B buffers; GEMM1: S = V @ Q^T ----
        ld_tile(g_q_hi + ((size_t)h * N_TOK + jt * 128) * D, D, Bhi);
        ld_tile(g_q_lo + ((size_t)h * N_TOK + jt * 128) * D, D, Blo);
        __syncthreads();

        FragC s[2][4];
        #pragma unroll
        for (int i = 0; i < 2; i++)
            #pragma unroll
            for (int j = 0; j < 4; j++) wmma::fill_fragment(s[i][j], 0.f);
        gemm3_tile(s, Ahi, Alo, Bhi, Blo, r0, c0);
        __syncthreads();   // everyone done reading Q before S overwrites it

        #pragma unroll
        for (int i = 0; i < 2; i++)
            #pragma unroll
            for (int j = 0; j < 4; j++)
                wmma::store_matrix_sync(&Ssm[(r0 + 16 * i) * LDS_ + c0 + 16 * j],
                                        s[i][j], LDS_, wmma::mem_row_major);
        __syncthreads();

        // ---- softmax pass 1: row max (thread owns half a row; conflict-free) ----
        {
            float lmax = -INFINITY;
            const float4* sp = (const float4*)&Ssm[row * LDS_ + half * 64];
            #pragma unroll
            for (int q4 = 0; q4 < 16; q4++) {
                float4 v4 = sp[q4];
                lmax = fmaxf(lmax, fmaxf(fmaxf(v4.x, v4.y), fmaxf(v4.z, v4.w)));
            }
            red[tid] = lmax;
        }
        __syncthreads();
        if (tid < 128) {
            float mo = m_s[tid];
            float mn = fmaxf(mo, fmaxf(red[tid], red[tid + 128]));
            m_s[tid] = mn;
            fac[tid] = __expf(mo - mn);
        }
        __syncthreads();

        // ---- softmax pass 2: exp, row sums, pack P hi/lo ----
        {
            float mn = m_s[row];
            float lsum = 0.f;
            __nv_bfloat16* ph = Phi + row * LDB + half * 64;
            __nv_bfloat16* pl = Plo + row * LDB + half * 64;
            #pragma unroll
            for (int g = 0; g < 8; g++) {
                uint32_t hw[4], lw[4];
                #pragma unroll
                for (int q = 0; q < 4; q++) {
                    int col = half * 64 + g * 8 + 2 * q;
                    float a  = __expf(Ssm[row * LDS_ + col]     - mn);
                    float b2 = __expf(Ssm[row * LDS_ + col + 1] - mn);
                    lsum += a + b2;
                    float la, lb;
                    hw[q] = pack_hi(a, b2, la, lb);
                    lw[q] = pack2(la, lb);
                }
                ((uint4*)ph)[g] = make_uint4(hw[0], hw[1], hw[2], hw[3]);
                ((uint4*)pl)[g] = make_uint4(lw[0], lw[1], lw[2], lw[3]);
            }
            red[tid] = lsum;
        }
        __syncthreads();
        if (tid < 128) l_s[tid] = l_s[tid] * fac[tid] + red[tid] + red[tid + 128];

        // ---- rescale O only when some row max changed (rare) ----
        int need = __syncthreads_or(tid < 128 && jt > 0 && fac[tid] != 1.0f);
        if (need && jt > 0) {
            #pragma unroll
            for (int i = 0; i < 2; i++)
                #pragma unroll
                for (int j = 0; j < 4; j++)
                    wmma::store_matrix_sync(&Ssm[(r0 + 16 * i) * LDS_ + c0 + 16 * j],
                                            o[i][j], LDS_, wmma::mem_row_major);
            __syncthreads();
            {
                float f = fac[row];
                float4* sp = (float4*)&Ssm[row * LDS_ + half * 64];
                #pragma unroll
                for (int q4 = 0; q4 < 16; q4++) {
                    float4 v4 = sp[q4];
                    v4.x *= f; v4.y *= f; v4.z *= f; v4.w *= f;
                    sp[q4] = v4;
                }
            }
            __syncthreads();
            #pragma unroll
            for (int i = 0; i < 2; i++)
                #pragma unroll
                for (int j = 0; j < 4; j++)
                    wmma::load_matrix_sync(o[i][j],
                                           &Ssm[(r0 + 16 * i) * LDS_ + c0 + 16 * j],
                                           LDS_, wmma::mem_row_major);
            __syncthreads();
        }

        // ---- K^T chunk -> B buffers (overwrites S); GEMM2: O += P @ K ----
        ld_tile(g_kT_hi + (size_t)h * D * N_TOK + (size_t)jt * 128, N_TOK, Bhi);
        ld_tile(g_kT_lo + (size_t)h * D * N_TOK + (size_t)jt * 128, N_TOK, Blo);
        __syncthreads();
        gemm3_tile(o, Phi, Plo, Bhi, Blo, r0, c0);
        __syncthreads();   // done reading P/B before next chunk overwrites
    }

    // ---- epilogue: O -> SMEM, normalize, split, store ----
    #pragma unroll
    for (int i = 0; i < 2; i++)
        #pragma unroll
        for (int j = 0; j < 4; j++)
            wmma::store_matrix_sync(&Ssm[(r0 + 16 * i) * LDS_ + c0 + 16 * j],
                                    o[i][j], LDS_, wmma::mem_row_major);
    __syncthreads();
    {
        float inv = 1.f / l_s[row];
        __nv_bfloat16* oh = g_att_hi + (size_t)(n0 + row) * (H * D) + h * D + half * 64;
        __nv_bfloat16* ol = g_att_lo + (size_t)(n0 + row) * (H * D) + h * D + half * 64;
        #pragma unroll
        for (int g = 0; g < 8; g++) {
            uint32_t hw[4], lw[4];
            #pragma unroll
            for (int q = 0; q < 4; q++) {
                int col = half * 64 + g * 8 + 2 * q;
                float a  = Ssm[row * LDS_ + col]     * inv;
                float b2 = Ssm[row * LDS_ + col + 1] * inv;
                float la, lb;
                hw[q] = pack_hi(a, b2, la, lb);
                lw[q] = pack2(la, lb);
            }
            ((uint4*)oh)[g] = make_uint4(hw[0], hw[1], hw[2], hw[3]);
            ((uint4*)ol)[g] = make_uint4(lw[0], lw[1], lw[2], lw[3]);
        }
    }
}

// ===========================================================================
// Kernel C: out[n][f] = att[n][:1024] @ WoT^T + bo, 8 K-tiles.
// grid 32, block 256.
// ===========================================================================
__global__ void __launch_bounds__(256, 1)
oproj_tc_kernel(const float* __restrict__ bo, float* __restrict__ out) {
    extern __shared__ char sm[];
    __nv_bfloat16* Ahi = (__nv_bfloat16*)(sm + OFF_AHI);
    __nv_bfloat16* Alo = (__nv_bfloat16*)(sm + OFF_ALO);
    __nv_bfloat16* Bhi = (__nv_bfloat16*)(sm + OFF_BHI);
    __nv_bfloat16* Blo = (__nv_bfloat16*)(sm + OFF_BLO);
    float* Ssm = (float*)(sm + OFF_PHI);
    float* bias = (float*)(sm + OFF_BIAS);

    int tid = threadIdx.x, wid = tid >> 5;
    int n0 = blockIdx.x * 128;
    int r0 = (wid & 3) * 32, c0 = (wid >> 2) * 64;
    if (tid < 128) bias[tid] = bo[tid];

    FragC acc[2][4];
    #pragma unroll
    for (int i = 0; i < 2; i++)
        #pragma unroll
        for (int j = 0; j < 4; j++) wmma::fill_fragment(acc[i][j], 0.f);

    for (int kt = 0; kt < 8; kt++) {
        ld_tile(g_att_hi + (size_t)n0 * (H * D) + kt * 128, H * D, Ahi);
        ld_tile(g_att_lo + (size_t)n0 * (H * D) + kt * 128, H * D, Alo);
        ld_tile(g_WoT_hi + kt * 128, H * D, Bhi);
        ld_tile(g_WoT_lo + kt * 128, H * D, Blo);
        __syncthreads();
        gemm3_tile(acc, Ahi, Alo, Bhi, Blo, r0, c0);
        __syncthreads();
    }

    #pragma unroll
    for (int i = 0; i < 2; i++)
        #pragma unroll
        for (int j = 0; j < 4; j++)
            wmma::store_matrix_sync(&Ssm[(r0 + 16 * i) * LDS_ + c0 + 16 * j],
                                    acc[i][j], LDS_, wmma::mem_row_major);
    __syncthreads();

    int row = tid & 127, half = tid >> 7;
    float* op = out + (size_t)(n0 + row) * D + half * 64;
    #pragma unroll
    for (int q4 = 0; q4 < 16; q4++) {
        int col = half * 64 + q4 * 4;
        float4 v4 = *(const float4*)&Ssm[row * LDS_ + col];
        v4.x += bias[col];     v4.y += bias[col + 1];
        v4.z += bias[col + 2]; v4.w += bias[col + 3];
        ((float4*)op)[q4] = v4;
    }
}

// ===========================================================================
extern "C" void kernel_launch(void* const* d_in, const int* in_sizes, int n_in,
                              void* d_out, int out_size) {
    const float* x  = (const float*)d_in[0];
    const float* Wq = (const float*)d_in[1];
    const float* bq = (const float*)d_in[2];
    const float* Wk = (const float*)d_in[3];
    const float* bk = (const float*)d_in[4];
    const float* Wv = (const float*)d_in[5];
    const float* bv = (const float*)d_in[6];
    const float* Wo = (const float*)d_in[7];
    const float* bo = (const float*)d_in[8];
    float* out = (float*)d_out;

    cudaFuncSetAttribute(qkv_tc_kernel,  cudaFuncAttributeMaxDynamicSharedMemorySize, SM_BYTES);
    cudaFuncSetAttribute(attn_tc_kernel, cudaFuncAttributeMaxDynamicSharedMemorySize, SM_BYTES);
    cudaFuncSetAttribute(oproj_tc_kernel, cudaFuncAttributeMaxDynamicSharedMemorySize, SM_BYTES);

    prep_kernel<<<256, 256>>>(x, Wq, Wk, Wv, Wo);
    qkv_tc_kernel<<<dim3(32, 24), 256, SM_BYTES>>>(bq, bk, bv);
    attn_tc_kernel<<<dim3(32, H), 256, SM_BYTES>>>();
    oproj_tc_kernel<<<32, 256, SM_BYTES>>>(bo, out);
}